// round 12
// baseline (speedup 1.0000x reference)
#include <cuda_runtime.h>
#include <cuda_fp16.h>
#include <math.h>
#include <stdint.h>

// Problem: z (8192 x 512 fp32) -> NT-Xent loss scalar (fp32)
#define TWO_N 8192
#define NHALF 4096
#define DDIM  512
#define INV_T 2.0f
// exp(2*s) = 2^(K2E*s); K2E folded into fp8 data as sqrt(K2E) on each side.
#define SCALE_FP8 1.69864944f        // sqrt(2 * log2(e))

// Tiling: 128x128 CTA tiles over the symmetric sim matrix, upper triangle only.
#define TM 128
#define NT (TWO_N / TM)              // 64
#define NTILES (NT * (NT + 1) / 2)   // 2080
#define KC 128                       // K chunk in fp8 elems (= 128B per row)
#define NCHUNK (DDIM / KC)           // 4
#define CHUNK_BYTES 16384            // 128 rows x 128 B, contiguous in g_z8 tiled layout
#define GRID 296                     // persistent CTAs (2 per SM on 148 SMs)

// SMEM: [0,24) mbarriers (3), stage s at 1024 + s*32768 (A 16KB + B 16KB)
#define NSTAGE 3
#define SM_MBAR   0
#define SM_TILES  1024
#define STAGE_BYTES 32768
#define SMEM_BYTES (SM_TILES + NSTAGE * STAGE_BYTES)   // 99328 -> occ 2
#define CHUNK_TX   32768             // A+B bytes per stage

// Scratch (no cudaMalloc allowed).
// g_z8 layout: [tile(64)][chunk(4)][row(128)][128B], rows XOR-swizzled:
//   byte (r, cu, rem) stored at r*128 + ((cu ^ (r&7))<<4) + rem
__device__ uint8_t g_z8[TWO_N * DDIM];   // 4 MB
__device__ float g_sumexp[TWO_N];
__device__ float g_pos[TWO_N];
__device__ int g_count;                  // CTA completion counter (reset by consumer)

__device__ __forceinline__ uint32_t smem_u32(const void* p) {
    uint32_t a;
    asm("{ .reg .u64 t; cvta.to.shared.u64 t, %1; cvt.u32.u64 %0, t; }" : "=r"(a) : "l"(p));
    return a;
}
__device__ __forceinline__ uint16_t pack_e4m3x2(float lo, float hi) {
    uint16_t r;
    asm("cvt.rn.satfinite.e4m3x2.f32 %0, %1, %2;" : "=h"(r) : "f"(hi), "f"(lo));
    return r;
}
__device__ __forceinline__ void mbar_init(uint32_t m, uint32_t cnt) {
    asm volatile("mbarrier.init.shared.b64 [%0], %1;" :: "r"(m), "r"(cnt) : "memory");
}
__device__ __forceinline__ void mbar_expect_tx(uint32_t m, uint32_t bytes) {
    asm volatile("mbarrier.arrive.expect_tx.shared.b64 _, [%0], %1;" :: "r"(m), "r"(bytes) : "memory");
}
__device__ __forceinline__ void mbar_wait(uint32_t m, uint32_t parity) {
    uint32_t done;
    asm volatile(
        "{\n\t.reg .pred p;\n\t"
        "mbarrier.try_wait.parity.acquire.cta.shared::cta.b64 p, [%1], %2;\n\t"
        "selp.b32 %0, 1, 0, p;\n\t}"
        : "=r"(done) : "r"(m), "r"(parity) : "memory");
    while (!done) {
        asm volatile(
            "{\n\t.reg .pred p;\n\t"
            "mbarrier.try_wait.parity.acquire.cta.shared::cta.b64 p, [%1], %2, 0x989680;\n\t"
            "selp.b32 %0, 1, 0, p;\n\t}"
            : "=r"(done) : "r"(m), "r"(parity) : "memory");
    }
}
// Bulk async copy gmem -> smem, completion via mbarrier tx bytes.
#define BULK_G2S(dst, src, size, mbar) \
    asm volatile("cp.async.bulk.shared::cluster.global.mbarrier::complete_tx::bytes " \
                 "[%0], [%1], %2, [%3];" \
                 :: "r"(dst), "l"(src), "r"(size), "r"(mbar) : "memory")

#define LDMATRIX_X4(r, addr) \
    asm volatile("ldmatrix.sync.aligned.m8n8.x4.shared.b16 {%0,%1,%2,%3}, [%4];" \
        : "=r"((r)[0]), "=r"((r)[1]), "=r"((r)[2]), "=r"((r)[3]) : "r"(addr))

// fp8 MMA with f16 accumulators: D/C are 2 regs (4 halves).
#define MMA_FP8_F16(c, a, b0, b1) \
    asm volatile("mma.sync.aligned.m16n8k32.row.col.f16.e4m3.e4m3.f16 " \
        "{%0,%1}, {%2,%3,%4,%5}, {%6,%7}, {%0,%1};" \
        : "+r"((c)[0]), "+r"((c)[1]) \
        : "r"((a)[0]), "r"((a)[1]), "r"((a)[2]), "r"((a)[3]), "r"(b0), "r"(b1))

// Decode upper-triangular linear tile index -> (i, j), j >= i.
__device__ __forceinline__ void decode_tile(int t, int& i, int& j) {
    i = 0;
    while (t >= NT - i) { t -= NT - i; ++i; }
    j = i + t;
}

// ---------------------------------------------------------------------------
// Kernel 1: fused L2-normalize (fp8 pack with folded exp2 scale) + positive
// sim + sumexp zeroing. One block (128 threads) per row.
// ---------------------------------------------------------------------------
__global__ void normpos_kernel(const float* __restrict__ z, uint8_t* __restrict__ z8,
                               float* __restrict__ pos, float* __restrict__ sumexp) {
    int row = blockIdx.x;
    int prow = row ^ NHALF;
    int t = threadIdx.x;
    float4 v = reinterpret_cast<const float4*>(z + (size_t)row * DDIM)[t];
    float4 w = reinterpret_cast<const float4*>(z + (size_t)prow * DDIM)[t];
    float ss = v.x * v.x + v.y * v.y + v.z * v.z + v.w * v.w;
    float pp = w.x * w.x + w.y * w.y + w.z * w.z + w.w * w.w;
    float ab = v.x * w.x + v.y * w.y + v.z * w.z + v.w * w.w;
    #pragma unroll
    for (int off = 16; off > 0; off >>= 1) {
        ss += __shfl_xor_sync(0xffffffffu, ss, off);
        pp += __shfl_xor_sync(0xffffffffu, pp, off);
        ab += __shfl_xor_sync(0xffffffffu, ab, off);
    }
    __shared__ float wsum[4][3];
    if ((t & 31) == 0) {
        wsum[t >> 5][0] = ss; wsum[t >> 5][1] = pp; wsum[t >> 5][2] = ab;
    }
    __syncthreads();
    float tss = wsum[0][0] + wsum[1][0] + wsum[2][0] + wsum[3][0];
    float tpp = wsum[0][1] + wsum[1][1] + wsum[2][1] + wsum[3][1];
    float tab = wsum[0][2] + wsum[1][2] + wsum[2][2] + wsum[3][2];

    float scale = SCALE_FP8 / fmaxf(sqrtf(tss), 1e-12f);
    uint16_t w0 = pack_e4m3x2(v.x * scale, v.y * scale);
    uint16_t w1 = pack_e4m3x2(v.z * scale, v.w * scale);
    uint32_t word = (uint32_t)w0 | ((uint32_t)w1 << 16);

    int tileIdx = row >> 7, r = row & 127;
    int b = t * 4;
    int chunk = b >> 7;
    int off = b & 127;
    int cu = off >> 4, rem = off & 15;
    size_t base = ((size_t)(tileIdx * NCHUNK + chunk) * 128 + r) * 128;
    *reinterpret_cast<uint32_t*>(z8 + base + (((cu ^ (r & 7)) << 4) + rem)) = word;

    if (t == 0) {
        pos[row] = tab * rsqrtf(tss * tpp) * INV_T;
        sumexp[row] = 0.0f;
    }
}

// ---------------------------------------------------------------------------
// Kernel 2: persistent fp8 MMA tile kernel. Each CTA streams chunks of its
// strided tile list through a 3-stage buffer that crosses tile boundaries,
// so the next tile's loads overlap the current tile's epilogue.
// ---------------------------------------------------------------------------
__global__ void __launch_bounds__(256, 2)
tile_kernel(const uint8_t* __restrict__ z8, float* __restrict__ sumexp,
            const float* __restrict__ pos, float* __restrict__ out) {
    extern __shared__ char smem[];
    const uint32_t sbase = smem_u32(smem);
    const int tid = threadIdx.x;
    const int lane = tid & 31;
    const int wid = tid >> 5;
    const int warpRow = wid >> 2;          // 0..1
    const int warpCol = wid & 3;           // 0..3

    // Fragment addressing: row r, 16B-unit col cu -> r*128 + ((cu ^ (r&7))<<4)
    const int lane15 = lane & 15;
    const int hi = lane >> 4;
    uint32_t aRow[4], aSw[4], bRow[2], bSw[2];
    #pragma unroll
    for (int mi = 0; mi < 4; ++mi) {
        int r = warpRow * 64 + mi * 16 + lane15;
        aRow[mi] = r << 7; aSw[mi] = r & 7;
    }
    #pragma unroll
    for (int nh = 0; nh < 2; ++nh) {
        int r = warpCol * 32 + nh * 16 + lane15;
        bRow[nh] = r << 7; bSw[nh] = r & 7;
    }

    // Init barriers once, then issue the first 3 chunks (all from first tile).
    if (tid == 0) {
        #pragma unroll
        for (int s = 0; s < NSTAGE; ++s) mbar_init(sbase + SM_MBAR + 8 * s, 1);
        asm volatile("fence.proxy.async.shared::cta;" ::: "memory");
        int i0, j0;
        decode_tile(blockIdx.x, i0, j0);
        const uint8_t* aT = z8 + (size_t)i0 * NCHUNK * CHUNK_BYTES;
        const uint8_t* bT = z8 + (size_t)j0 * NCHUNK * CHUNK_BYTES;
        #pragma unroll
        for (int s = 0; s < NSTAGE; ++s) {
            uint32_t mb = sbase + SM_MBAR + 8 * s;
            uint32_t dst = sbase + SM_TILES + s * STAGE_BYTES;
            mbar_expect_tx(mb, CHUNK_TX);
            BULK_G2S(dst,               aT + s * CHUNK_BYTES, CHUNK_BYTES, mb);
            BULK_G2S(dst + CHUNK_BYTES, bT + s * CHUNK_BYTES, CHUNK_BYTES, mb);
        }
    }
    __syncthreads();

    int q = 0;                              // global chunk stream position
    for (int tile = blockIdx.x, k = 0; tile < NTILES; tile += GRID, ++k) {
        int i, j;
        decode_tile(tile, i, j);
        const bool diag = (i == j);

        // f16x2 accumulators
        uint32_t acc[4][4][2];
        #pragma unroll
        for (int mi = 0; mi < 4; ++mi)
            #pragma unroll
            for (int ni = 0; ni < 4; ++ni) { acc[mi][ni][0] = 0u; acc[mi][ni][1] = 0u; }

        #pragma unroll
        for (int c = 0; c < NCHUNK; ++c, ++q) {
            const int s = q % NSTAGE;
            const uint32_t mb = sbase + SM_MBAR + 8 * s;
            mbar_wait(mb, (q / NSTAGE) & 1);

            const uint32_t abase = sbase + SM_TILES + s * STAGE_BYTES;
            const uint32_t bbase = abase + CHUNK_BYTES;

            #pragma unroll
            for (int ks = 0; ks < 4; ++ks) {
                const uint32_t cu = 2 * ks + hi;
                uint32_t ra[4][4], rb[2][4];
                #pragma unroll
                for (int mi = 0; mi < 4; ++mi)
                    LDMATRIX_X4(ra[mi], abase + aRow[mi] + (((cu ^ aSw[mi])) << 4));
                #pragma unroll
                for (int nh = 0; nh < 2; ++nh)
                    LDMATRIX_X4(rb[nh], bbase + bRow[nh] + (((cu ^ bSw[nh])) << 4));
                #pragma unroll
                for (int mi = 0; mi < 4; ++mi)
                    #pragma unroll
                    for (int ni = 0; ni < 4; ++ni) {
                        const int nh = ni >> 1, sel = ni & 1;
                        MMA_FP8_F16(acc[mi][ni], ra[mi], rb[nh][sel], rb[nh][2 + sel]);
                    }
            }

            // All warps consumed stage s; refill with chunk q+NSTAGE (may be next tile).
            __syncthreads();
            if (tid == 0) {
                int qn = q + NSTAGE;
                int kn = qn >> 2;
                int tn = blockIdx.x + kn * GRID;
                if (tn < NTILES) {
                    int i2, j2;
                    decode_tile(tn, i2, j2);
                    int c2 = qn & 3;
                    const uint8_t* aT = z8 + (size_t)i2 * NCHUNK * CHUNK_BYTES + c2 * CHUNK_BYTES;
                    const uint8_t* bT = z8 + (size_t)j2 * NCHUNK * CHUNK_BYTES + c2 * CHUNK_BYTES;
                    mbar_expect_tx(mb, CHUNK_TX);
                    BULK_G2S(abase, aT, CHUNK_BYTES, mb);
                    BULK_G2S(bbase, bT, CHUNK_BYTES, mb);
                }
            }
        }

        // Epilogue: exp2(acc) = exp(2*sim); row partials (mi,h), col partials (ni,e).
        const int m0 = warpRow * 64, n0 = warpCol * 32;
        const int rowBase = i * TM, colBase = j * TM;
        float rowp[4][2], colp[4][2];

        if (!diag) {
            __half2 rowh[4][2], colh[4];
            #pragma unroll
            for (int mi = 0; mi < 4; ++mi) { rowh[mi][0] = __half2(); rowh[mi][1] = __half2(); }
            #pragma unroll
            for (int ni = 0; ni < 4; ++ni) colh[ni] = __half2();

            #pragma unroll
            for (int mi = 0; mi < 4; ++mi)
                #pragma unroll
                for (int ni = 0; ni < 4; ++ni)
                    #pragma unroll
                    for (int h = 0; h < 2; ++h) {
                        __half2 ex = h2exp2(*reinterpret_cast<const __half2*>(&acc[mi][ni][h]));
                        rowh[mi][h] = __hadd2(rowh[mi][h], ex);
                        colh[ni] = __hadd2(colh[ni], ex);
                    }
            #pragma unroll
            for (int mi = 0; mi < 4; ++mi)
                #pragma unroll
                for (int h = 0; h < 2; ++h) {
                    float2 f = __half22float2(rowh[mi][h]);
                    rowp[mi][h] = f.x + f.y;
                }
            #pragma unroll
            for (int ni = 0; ni < 4; ++ni) {
                float2 f = __half22float2(colh[ni]);
                colp[ni][0] = f.x; colp[ni][1] = f.y;
            }
        } else {
            #pragma unroll
            for (int a = 0; a < 4; ++a) { rowp[a][0] = rowp[a][1] = 0.f; colp[a][0] = colp[a][1] = 0.f; }
            #pragma unroll
            for (int mi = 0; mi < 4; ++mi)
                #pragma unroll
                for (int ni = 0; ni < 4; ++ni)
                    #pragma unroll
                    for (int h = 0; h < 2; ++h) {
                        float2 f = __half22float2(*reinterpret_cast<const __half2*>(&acc[mi][ni][h]));
                        #pragma unroll
                        for (int e = 0; e < 2; ++e) {
                            float ex = exp2f(e ? f.y : f.x);
                            int lr = m0 + mi * 16 + (lane >> 2) + 8 * h;
                            int lc = n0 + ni * 8 + (lane & 3) * 2 + e;
                            if (lr == lc) ex = 0.f;
                            rowp[mi][h] += ex;
                            colp[ni][e] += ex;
                        }
                    }
        }

        #pragma unroll
        for (int mi = 0; mi < 4; ++mi)
            #pragma unroll
            for (int h = 0; h < 2; ++h) {
                float v = rowp[mi][h];
                v += __shfl_xor_sync(0xffffffffu, v, 1);
                v += __shfl_xor_sync(0xffffffffu, v, 2);
                rowp[mi][h] = v;
            }
        if ((lane & 3) == 0) {
            #pragma unroll
            for (int mi = 0; mi < 4; ++mi)
                #pragma unroll
                for (int h = 0; h < 2; ++h)
                    atomicAdd(&sumexp[rowBase + m0 + mi * 16 + (lane >> 2) + 8 * h], rowp[mi][h]);
        }

        if (!diag) {
            #pragma unroll
            for (int ni = 0; ni < 4; ++ni)
                #pragma unroll
                for (int e = 0; e < 2; ++e) {
                    float v = colp[ni][e];
                    v += __shfl_xor_sync(0xffffffffu, v, 4);
                    v += __shfl_xor_sync(0xffffffffu, v, 8);
                    v += __shfl_xor_sync(0xffffffffu, v, 16);
                    colp[ni][e] = v;
                }
            if (lane < 4) {
                #pragma unroll
                for (int ni = 0; ni < 4; ++ni)
                    #pragma unroll
                    for (int e = 0; e < 2; ++e)
                        atomicAdd(&sumexp[colBase + n0 + ni * 8 + lane * 2 + e], colp[ni][e]);
            }
        }
    }

    // Last-CTA loss reduction: loss = mean( log(sumexp) - pos ).
    __threadfence();
    __shared__ int isLast;
    if (tid == 0) isLast = (atomicAdd(&g_count, 1) == GRID - 1);
    __syncthreads();
    if (isLast) {
        float s = 0.f;
        #pragma unroll
        for (int qq = 0; qq < TWO_N / 256; ++qq)
            s += __logf(sumexp[qq * 256 + tid]) - pos[qq * 256 + tid];
        #pragma unroll
        for (int off = 16; off > 0; off >>= 1)
            s += __shfl_xor_sync(0xffffffffu, s, off);
        __shared__ float wred[8];
        if (lane == 0) wred[wid] = s;
        __syncthreads();
        if (tid == 0) {
            float tot = 0.f;
            #pragma unroll
            for (int kk = 0; kk < 8; ++kk) tot += wred[kk];
            out[0] = tot * (1.0f / (float)TWO_N);
            g_count = 0;                 // reset for next graph replay
        }
    }
}

// ---------------------------------------------------------------------------
extern "C" void kernel_launch(void* const* d_in, const int* in_sizes, int n_in,
                              void* d_out, int out_size) {
    const float* z = (const float*)d_in[0];
    float* out = (float*)d_out;

    uint8_t* z8;   cudaGetSymbolAddress((void**)&z8, g_z8);
    float* sumexp; cudaGetSymbolAddress((void**)&sumexp, g_sumexp);
    float* pos;    cudaGetSymbolAddress((void**)&pos, g_pos);

    cudaFuncSetAttribute(tile_kernel, cudaFuncAttributeMaxDynamicSharedMemorySize, SMEM_BYTES);

    normpos_kernel<<<TWO_N, 128>>>(z, z8, pos, sumexp);
    tile_kernel<<<GRID, 256, SMEM_BYTES>>>(z8, sumexp, pos, out);
}

// round 14
// speedup vs baseline: 1.0935x; 1.0935x over previous
#include <cuda_runtime.h>
#include <cuda_fp16.h>
#include <math.h>
#include <stdint.h>

// Problem: z (8192 x 512 fp32) -> NT-Xent loss scalar (fp32)
#define TWO_N 8192
#define NHALF 4096
#define DDIM  512
#define INV_T 2.0f
// exp(2*s) = 2^(K2E*s); K2E folded into fp8 data as sqrt(K2E) on each side.
#define SCALE_FP8 1.69864944f        // sqrt(2 * log2(e))

// Tiling: 128x128 CTA tiles over the symmetric sim matrix, upper triangle only.
#define TM 128
#define NT (TWO_N / TM)              // 64
#define NTILES (NT * (NT + 1) / 2)   // 2080
#define KC 128                       // K chunk in fp8 elems (= 128B per row)
#define NCHUNK (DDIM / KC)           // 4
#define CHUNK_BYTES 16384            // 128 rows x 128 B, contiguous in g_z8 tiled layout

// SMEM: [0,24) full mbarriers (3), [24,32) empty mbarrier (stage 0 reuse),
// stage s at 1024 + s*32768 (A 16KB + B 16KB)
#define NSTAGE 3
#define SM_MBAR   0
#define SM_EMPTY  24
#define SM_TILES  1024
#define STAGE_BYTES 32768
#define SMEM_BYTES (SM_TILES + NSTAGE * STAGE_BYTES)   // 99328 -> occ 2
#define CHUNK_TX   32768             // A+B bytes per stage

// Scratch (no cudaMalloc allowed).
// g_z8 layout: [tile(64)][chunk(4)][row(128)][128B], rows XOR-swizzled:
//   byte (r, cu, rem) stored at r*128 + ((cu ^ (r&7))<<4) + rem
__device__ uint8_t g_z8[TWO_N * DDIM];   // 4 MB
__device__ float g_sumexp[TWO_N];
__device__ float g_pos[TWO_N];
__device__ int g_count;                  // tile completion counter (reset by consumer)

__device__ __forceinline__ uint32_t smem_u32(const void* p) {
    uint32_t a;
    asm("{ .reg .u64 t; cvta.to.shared.u64 t, %1; cvt.u32.u64 %0, t; }" : "=r"(a) : "l"(p));
    return a;
}
__device__ __forceinline__ uint16_t pack_e4m3x2(float lo, float hi) {
    uint16_t r;
    asm("cvt.rn.satfinite.e4m3x2.f32 %0, %1, %2;" : "=h"(r) : "f"(hi), "f"(lo));
    return r;
}
__device__ __forceinline__ void mbar_init(uint32_t m, uint32_t cnt) {
    asm volatile("mbarrier.init.shared.b64 [%0], %1;" :: "r"(m), "r"(cnt) : "memory");
}
__device__ __forceinline__ void mbar_arrive(uint32_t m) {
    asm volatile("mbarrier.arrive.shared.b64 _, [%0];" :: "r"(m) : "memory");
}
__device__ __forceinline__ void mbar_expect_tx(uint32_t m, uint32_t bytes) {
    asm volatile("mbarrier.arrive.expect_tx.shared.b64 _, [%0], %1;" :: "r"(m), "r"(bytes) : "memory");
}
__device__ __forceinline__ void mbar_wait(uint32_t m, uint32_t parity) {
    uint32_t done;
    asm volatile(
        "{\n\t.reg .pred p;\n\t"
        "mbarrier.try_wait.parity.acquire.cta.shared::cta.b64 p, [%1], %2;\n\t"
        "selp.b32 %0, 1, 0, p;\n\t}"
        : "=r"(done) : "r"(m), "r"(parity) : "memory");
    while (!done) {
        asm volatile(
            "{\n\t.reg .pred p;\n\t"
            "mbarrier.try_wait.parity.acquire.cta.shared::cta.b64 p, [%1], %2, 0x989680;\n\t"
            "selp.b32 %0, 1, 0, p;\n\t}"
            : "=r"(done) : "r"(m), "r"(parity) : "memory");
    }
}
// Bulk async copy gmem -> smem, completion via mbarrier tx bytes.
#define BULK_G2S(dst, src, size, mbar) \
    asm volatile("cp.async.bulk.shared::cluster.global.mbarrier::complete_tx::bytes " \
                 "[%0], [%1], %2, [%3];" \
                 :: "r"(dst), "l"(src), "r"(size), "r"(mbar) : "memory")

#define LDMATRIX_X4(r, addr) \
    asm volatile("ldmatrix.sync.aligned.m8n8.x4.shared.b16 {%0,%1,%2,%3}, [%4];" \
        : "=r"((r)[0]), "=r"((r)[1]), "=r"((r)[2]), "=r"((r)[3]) : "r"(addr))

// fp8 MMA with f16 accumulators: D/C are 2 regs (4 halves).
#define MMA_FP8_F16(c, a, b0, b1) \
    asm volatile("mma.sync.aligned.m16n8k32.row.col.f16.e4m3.e4m3.f16 " \
        "{%0,%1}, {%2,%3,%4,%5}, {%6,%7}, {%0,%1};" \
        : "+r"((c)[0]), "+r"((c)[1]) \
        : "r"((a)[0]), "r"((a)[1]), "r"((a)[2]), "r"((a)[3]), "r"(b0), "r"(b1))

// ---------------------------------------------------------------------------
// Kernel 1: fused L2-normalize (fp8 pack with folded exp2 scale) + positive
// sim + sumexp zeroing. One block (128 threads) per row.
// ---------------------------------------------------------------------------
__global__ void normpos_kernel(const float* __restrict__ z, uint8_t* __restrict__ z8,
                               float* __restrict__ pos, float* __restrict__ sumexp) {
    int row = blockIdx.x;
    int prow = row ^ NHALF;
    int t = threadIdx.x;
    float4 v = reinterpret_cast<const float4*>(z + (size_t)row * DDIM)[t];
    float4 w = reinterpret_cast<const float4*>(z + (size_t)prow * DDIM)[t];
    float ss = v.x * v.x + v.y * v.y + v.z * v.z + v.w * v.w;
    float pp = w.x * w.x + w.y * w.y + w.z * w.z + w.w * w.w;
    float ab = v.x * w.x + v.y * w.y + v.z * w.z + v.w * w.w;
    #pragma unroll
    for (int off = 16; off > 0; off >>= 1) {
        ss += __shfl_xor_sync(0xffffffffu, ss, off);
        pp += __shfl_xor_sync(0xffffffffu, pp, off);
        ab += __shfl_xor_sync(0xffffffffu, ab, off);
    }
    __shared__ float wsum[4][3];
    if ((t & 31) == 0) {
        wsum[t >> 5][0] = ss; wsum[t >> 5][1] = pp; wsum[t >> 5][2] = ab;
    }
    __syncthreads();
    float tss = wsum[0][0] + wsum[1][0] + wsum[2][0] + wsum[3][0];
    float tpp = wsum[0][1] + wsum[1][1] + wsum[2][1] + wsum[3][1];
    float tab = wsum[0][2] + wsum[1][2] + wsum[2][2] + wsum[3][2];

    float scale = SCALE_FP8 / fmaxf(sqrtf(tss), 1e-12f);
    uint16_t w0 = pack_e4m3x2(v.x * scale, v.y * scale);
    uint16_t w1 = pack_e4m3x2(v.z * scale, v.w * scale);
    uint32_t word = (uint32_t)w0 | ((uint32_t)w1 << 16);

    int tileIdx = row >> 7, r = row & 127;
    int b = t * 4;
    int chunk = b >> 7;
    int off = b & 127;
    int cu = off >> 4, rem = off & 15;
    size_t base = ((size_t)(tileIdx * NCHUNK + chunk) * 128 + r) * 128;
    *reinterpret_cast<uint32_t*>(z8 + base + (((cu ^ (r & 7)) << 4) + rem)) = word;

    if (t == 0) {
        pos[row] = tab * rsqrtf(tss * tpp) * INV_T;
        sumexp[row] = 0.0f;
    }
}

// ---------------------------------------------------------------------------
// Kernel 2: fp8 MMA (f16 accum) tile kernel. Barrier-free mainloop: the only
// stage reuse (chunk 3 -> stage 0) is guarded by an empty mbarrier that all
// threads arrive on after chunk 0; warps otherwise slide freely.
// ---------------------------------------------------------------------------
__global__ void __launch_bounds__(256, 2)
tile_kernel(const uint8_t* __restrict__ z8, float* __restrict__ sumexp,
            const float* __restrict__ pos, float* __restrict__ out) {
    extern __shared__ char smem[];
    const uint32_t sbase = smem_u32(smem);
    const int tid = threadIdx.x;
    const int lane = tid & 31;
    const int wid = tid >> 5;
    const int warpRow = wid >> 2;          // 0..1
    const int warpCol = wid & 3;           // 0..3

    // Map blockIdx.x -> upper-triangular tile (i, j), j >= i
    int t = blockIdx.x, i = 0;
    while (t >= NT - i) { t -= NT - i; ++i; }
    const int j = i + t;
    const bool diag = (i == j);
    const uint8_t* aTiles = z8 + (size_t)i * NCHUNK * CHUNK_BYTES;
    const uint8_t* bTiles = z8 + (size_t)j * NCHUNK * CHUNK_BYTES;

    // Init barriers + issue chunks 0..2 into stages 0..2.
    if (tid == 0) {
        #pragma unroll
        for (int s = 0; s < NSTAGE; ++s) mbar_init(sbase + SM_MBAR + 8 * s, 1);
        mbar_init(sbase + SM_EMPTY, 256);
        asm volatile("fence.proxy.async.shared::cta;" ::: "memory");
        #pragma unroll
        for (int s = 0; s < NSTAGE; ++s) {
            uint32_t mb = sbase + SM_MBAR + 8 * s;
            uint32_t dst = sbase + SM_TILES + s * STAGE_BYTES;
            mbar_expect_tx(mb, CHUNK_TX);
            BULK_G2S(dst,               aTiles + s * CHUNK_BYTES, CHUNK_BYTES, mb);
            BULK_G2S(dst + CHUNK_BYTES, bTiles + s * CHUNK_BYTES, CHUNK_BYTES, mb);
        }
    }
    __syncthreads();   // barrier inits visible before any wait

    // f16x2 accumulators: acc[mi][ni][h] packs cols (e=0,e=1) for row-half h.
    uint32_t acc[4][4][2];
    #pragma unroll
    for (int mi = 0; mi < 4; ++mi)
        #pragma unroll
        for (int ni = 0; ni < 4; ++ni) { acc[mi][ni][0] = 0u; acc[mi][ni][1] = 0u; }

    // Fragment addressing: row r, 16B-unit col cu -> r*128 + ((cu ^ (r&7))<<4)
    const int lane15 = lane & 15;
    const int hi = lane >> 4;
    uint32_t aRow[4], aSw[4], bRow[2], bSw[2];
    #pragma unroll
    for (int mi = 0; mi < 4; ++mi) {
        int r = warpRow * 64 + mi * 16 + lane15;
        aRow[mi] = r << 7; aSw[mi] = r & 7;
    }
    #pragma unroll
    for (int nh = 0; nh < 2; ++nh) {
        int r = warpCol * 32 + nh * 16 + lane15;
        bRow[nh] = r << 7; bSw[nh] = r & 7;
    }

    #pragma unroll
    for (int c = 0; c < NCHUNK; ++c) {
        const int s = c % NSTAGE;
        const uint32_t mb = sbase + SM_MBAR + 8 * s;
        mbar_wait(mb, (c < NSTAGE) ? 0 : 1);

        const uint32_t abase = sbase + SM_TILES + s * STAGE_BYTES;
        const uint32_t bbase = abase + CHUNK_BYTES;

        #pragma unroll
        for (int ks = 0; ks < 4; ++ks) {
            const uint32_t cu = 2 * ks + hi;
            uint32_t ra[4][4], rb[2][4];
            #pragma unroll
            for (int mi = 0; mi < 4; ++mi)
                LDMATRIX_X4(ra[mi], abase + aRow[mi] + (((cu ^ aSw[mi])) << 4));
            #pragma unroll
            for (int nh = 0; nh < 2; ++nh)
                LDMATRIX_X4(rb[nh], bbase + bRow[nh] + (((cu ^ bSw[nh])) << 4));
            #pragma unroll
            for (int mi = 0; mi < 4; ++mi)
                #pragma unroll
                for (int ni = 0; ni < 4; ++ni) {
                    const int nh = ni >> 1, sel = ni & 1;
                    MMA_FP8_F16(acc[mi][ni], ra[mi], rb[nh][sel], rb[nh][2 + sel]);
                }
        }

        // Only chunk 0's stage gets reused (chunk 3 -> stage 0): signal
        // consumption (non-blocking), and tid0 refills once all have read.
        if (c == 0) {
            mbar_arrive(sbase + SM_EMPTY);
            if (tid == 0) {
                mbar_wait(sbase + SM_EMPTY, 0);
                mbar_expect_tx(mb, CHUNK_TX);
                BULK_G2S(abase, aTiles + 3 * CHUNK_BYTES, CHUNK_BYTES, mb);
                BULK_G2S(bbase, bTiles + 3 * CHUNK_BYTES, CHUNK_BYTES, mb);
            }
        }
    }

    // Epilogue: exp2(acc) = exp(2*sim); row partials (mi,h), col partials (ni,e).
    const int m0 = warpRow * 64, n0 = warpCol * 32;
    const int rowBase = i * TM, colBase = j * TM;
    float rowp[4][2], colp[4][2];

    if (!diag) {
        __half2 rowh[4][2], colh[4];
        #pragma unroll
        for (int mi = 0; mi < 4; ++mi) { rowh[mi][0] = __half2(); rowh[mi][1] = __half2(); }
        #pragma unroll
        for (int ni = 0; ni < 4; ++ni) colh[ni] = __half2();

        #pragma unroll
        for (int mi = 0; mi < 4; ++mi)
            #pragma unroll
            for (int ni = 0; ni < 4; ++ni)
                #pragma unroll
                for (int h = 0; h < 2; ++h) {
                    __half2 ex = h2exp2(*reinterpret_cast<const __half2*>(&acc[mi][ni][h]));
                    rowh[mi][h] = __hadd2(rowh[mi][h], ex);
                    colh[ni] = __hadd2(colh[ni], ex);
                }
        #pragma unroll
        for (int mi = 0; mi < 4; ++mi)
            #pragma unroll
            for (int h = 0; h < 2; ++h) {
                float2 f = __half22float2(rowh[mi][h]);
                rowp[mi][h] = f.x + f.y;
            }
        #pragma unroll
        for (int ni = 0; ni < 4; ++ni) {
            float2 f = __half22float2(colh[ni]);
            colp[ni][0] = f.x; colp[ni][1] = f.y;
        }
    } else {
        #pragma unroll
        for (int a = 0; a < 4; ++a) { rowp[a][0] = rowp[a][1] = 0.f; colp[a][0] = colp[a][1] = 0.f; }
        #pragma unroll
        for (int mi = 0; mi < 4; ++mi)
            #pragma unroll
            for (int ni = 0; ni < 4; ++ni)
                #pragma unroll
                for (int h = 0; h < 2; ++h) {
                    float2 f = __half22float2(*reinterpret_cast<const __half2*>(&acc[mi][ni][h]));
                    #pragma unroll
                    for (int e = 0; e < 2; ++e) {
                        float ex = exp2f(e ? f.y : f.x);
                        int lr = m0 + mi * 16 + (lane >> 2) + 8 * h;
                        int lc = n0 + ni * 8 + (lane & 3) * 2 + e;
                        if (lr == lc) ex = 0.f;
                        rowp[mi][h] += ex;
                        colp[ni][e] += ex;
                    }
                }
    }

    #pragma unroll
    for (int mi = 0; mi < 4; ++mi)
        #pragma unroll
        for (int h = 0; h < 2; ++h) {
            float v = rowp[mi][h];
            v += __shfl_xor_sync(0xffffffffu, v, 1);
            v += __shfl_xor_sync(0xffffffffu, v, 2);
            rowp[mi][h] = v;
        }
    if ((lane & 3) == 0) {
        #pragma unroll
        for (int mi = 0; mi < 4; ++mi)
            #pragma unroll
            for (int h = 0; h < 2; ++h)
                atomicAdd(&sumexp[rowBase + m0 + mi * 16 + (lane >> 2) + 8 * h], rowp[mi][h]);
    }

    if (!diag) {
        #pragma unroll
        for (int ni = 0; ni < 4; ++ni)
            #pragma unroll
            for (int e = 0; e < 2; ++e) {
                float v = colp[ni][e];
                v += __shfl_xor_sync(0xffffffffu, v, 4);
                v += __shfl_xor_sync(0xffffffffu, v, 8);
                v += __shfl_xor_sync(0xffffffffu, v, 16);
                colp[ni][e] = v;
            }
        if (lane < 4) {
            #pragma unroll
            for (int ni = 0; ni < 4; ++ni)
                #pragma unroll
                for (int e = 0; e < 2; ++e)
                    atomicAdd(&sumexp[colBase + n0 + ni * 8 + lane * 2 + e], colp[ni][e]);
        }
    }

    // Last-CTA loss reduction: loss = mean( log(sumexp) - pos ).
    __threadfence();
    __shared__ int isLast;
    if (tid == 0) isLast = (atomicAdd(&g_count, 1) == NTILES - 1);
    __syncthreads();
    if (isLast) {
        float s = 0.f;
        #pragma unroll
        for (int q = 0; q < TWO_N / 256; ++q)
            s += __logf(sumexp[q * 256 + tid]) - pos[q * 256 + tid];
        #pragma unroll
        for (int off = 16; off > 0; off >>= 1)
            s += __shfl_xor_sync(0xffffffffu, s, off);
        __shared__ float wred[8];
        if (lane == 0) wred[wid] = s;
        __syncthreads();
        if (tid == 0) {
            float tot = 0.f;
            #pragma unroll
            for (int k = 0; k < 8; ++k) tot += wred[k];
            out[0] = tot * (1.0f / (float)TWO_N);
            g_count = 0;                 // reset for next graph replay
        }
    }
}

// ---------------------------------------------------------------------------
extern "C" void kernel_launch(void* const* d_in, const int* in_sizes, int n_in,
                              void* d_out, int out_size) {
    const float* z = (const float*)d_in[0];
    float* out = (float*)d_out;

    uint8_t* z8;   cudaGetSymbolAddress((void**)&z8, g_z8);
    float* sumexp; cudaGetSymbolAddress((void**)&sumexp, g_sumexp);
    float* pos;    cudaGetSymbolAddress((void**)&pos, g_pos);

    cudaFuncSetAttribute(tile_kernel, cudaFuncAttributeMaxDynamicSharedMemorySize, SMEM_BYTES);

    normpos_kernel<<<TWO_N, 128>>>(z, z8, pos, sumexp);
    tile_kernel<<<NTILES, 256, SMEM_BYTES>>>(z8, sumexp, pos, out);
}

// round 16
// speedup vs baseline: 1.1157x; 1.0203x over previous
#include <cuda_runtime.h>
#include <cuda_fp16.h>
#include <math.h>
#include <stdint.h>

// Problem: z (8192 x 512 fp32) -> NT-Xent loss scalar (fp32)
#define TWO_N 8192
#define NHALF 4096
#define DDIM  512
#define INV_T 2.0f
// exp(2*s) = 2^(K2E*s); K2E folded into fp8 data as sqrt(K2E) on each side.
#define SCALE_FP8 1.69864944f        // sqrt(2 * log2(e))

// Tiling: 128x128 CTA tiles over the symmetric sim matrix, upper triangle only.
#define TM 128
#define NT (TWO_N / TM)              // 64
#define NTILES (NT * (NT + 1) / 2)   // 2080
#define KC 128                       // K chunk in fp8 elems (= 128B per row)
#define NCHUNK (DDIM / KC)           // 4
#define CHUNK_BYTES 16384            // 128 rows x 128 B, contiguous in g_z8 tiled layout

// SMEM: [0,24) full mbarriers (3), [24,32) empty mbarrier (stage 0 reuse),
// stage s at 1024 + s*32768 (A 16KB + B 16KB)
#define NSTAGE 3
#define SM_MBAR   0
#define SM_EMPTY  24
#define SM_TILES  1024
#define STAGE_BYTES 32768
#define SMEM_BYTES (SM_TILES + NSTAGE * STAGE_BYTES)   // 99328 -> occ 2
#define CHUNK_TX   32768             // A+B bytes per stage

// Scratch (no cudaMalloc allowed).
// g_z8 layout: [tile(64)][chunk(4)][row(128)][128B], rows XOR-swizzled:
//   byte (r, cu, rem) stored at r*128 + ((cu ^ (r&7))<<4) + rem
__device__ uint8_t g_z8[TWO_N * DDIM];   // 4 MB
__device__ float g_sumexp[TWO_N];
__device__ float g_pos[TWO_N];
__device__ int g_count;                  // tile completion counter (reset by consumer)

__device__ __forceinline__ uint32_t smem_u32(const void* p) {
    uint32_t a;
    asm("{ .reg .u64 t; cvta.to.shared.u64 t, %1; cvt.u32.u64 %0, t; }" : "=r"(a) : "l"(p));
    return a;
}
__device__ __forceinline__ uint16_t pack_e4m3x2(float lo, float hi) {
    uint16_t r;
    asm("cvt.rn.satfinite.e4m3x2.f32 %0, %1, %2;" : "=h"(r) : "f"(hi), "f"(lo));
    return r;
}
__device__ __forceinline__ void mbar_init(uint32_t m, uint32_t cnt) {
    asm volatile("mbarrier.init.shared.b64 [%0], %1;" :: "r"(m), "r"(cnt) : "memory");
}
__device__ __forceinline__ void mbar_arrive(uint32_t m) {
    asm volatile("mbarrier.arrive.shared.b64 _, [%0];" :: "r"(m) : "memory");
}
__device__ __forceinline__ void mbar_expect_tx(uint32_t m, uint32_t bytes) {
    asm volatile("mbarrier.arrive.expect_tx.shared.b64 _, [%0], %1;" :: "r"(m), "r"(bytes) : "memory");
}
__device__ __forceinline__ void mbar_wait(uint32_t m, uint32_t parity) {
    uint32_t done;
    asm volatile(
        "{\n\t.reg .pred p;\n\t"
        "mbarrier.try_wait.parity.acquire.cta.shared::cta.b64 p, [%1], %2;\n\t"
        "selp.b32 %0, 1, 0, p;\n\t}"
        : "=r"(done) : "r"(m), "r"(parity) : "memory");
    while (!done) {
        asm volatile(
            "{\n\t.reg .pred p;\n\t"
            "mbarrier.try_wait.parity.acquire.cta.shared::cta.b64 p, [%1], %2, 0x989680;\n\t"
            "selp.b32 %0, 1, 0, p;\n\t}"
            : "=r"(done) : "r"(m), "r"(parity) : "memory");
    }
}
// Bulk async copy gmem -> smem, completion via mbarrier tx bytes.
#define BULK_G2S(dst, src, size, mbar) \
    asm volatile("cp.async.bulk.shared::cluster.global.mbarrier::complete_tx::bytes " \
                 "[%0], [%1], %2, [%3];" \
                 :: "r"(dst), "l"(src), "r"(size), "r"(mbar) : "memory")

#define LDMATRIX_X4(r, addr) \
    asm volatile("ldmatrix.sync.aligned.m8n8.x4.shared.b16 {%0,%1,%2,%3}, [%4];" \
        : "=r"((r)[0]), "=r"((r)[1]), "=r"((r)[2]), "=r"((r)[3]) : "r"(addr))

// fp8 MMA with f16 accumulators: D/C are 2 regs (4 halves).
#define MMA_FP8_F16(c, a, b0, b1) \
    asm volatile("mma.sync.aligned.m16n8k32.row.col.f16.e4m3.e4m3.f16 " \
        "{%0,%1}, {%2,%3,%4,%5}, {%6,%7}, {%0,%1};" \
        : "+r"((c)[0]), "+r"((c)[1]) \
        : "r"((a)[0]), "r"((a)[1]), "r"((a)[2]), "r"((a)[3]), "r"(b0), "r"(b1))

// ---------------------------------------------------------------------------
// Kernel 1: fused L2-normalize + positive sim + zeroing for a ROW PAIR
// (row, row+NHALF). 4096 blocks x 128 threads; each block handles both rows
// of one positive pair (they share the pos dot), halving global traffic.
// ---------------------------------------------------------------------------
__global__ void normpos_kernel(const float* __restrict__ z, uint8_t* __restrict__ z8,
                               float* __restrict__ pos, float* __restrict__ sumexp) {
    int row = blockIdx.x;            // 0..NHALF-1
    int prow = row + NHALF;
    int t = threadIdx.x;
    float4 v = reinterpret_cast<const float4*>(z + (size_t)row * DDIM)[t];
    float4 w = reinterpret_cast<const float4*>(z + (size_t)prow * DDIM)[t];
    float ss = v.x * v.x + v.y * v.y + v.z * v.z + v.w * v.w;
    float pp = w.x * w.x + w.y * w.y + w.z * w.z + w.w * w.w;
    float ab = v.x * w.x + v.y * w.y + v.z * w.z + v.w * w.w;
    #pragma unroll
    for (int off = 16; off > 0; off >>= 1) {
        ss += __shfl_xor_sync(0xffffffffu, ss, off);
        pp += __shfl_xor_sync(0xffffffffu, pp, off);
        ab += __shfl_xor_sync(0xffffffffu, ab, off);
    }
    __shared__ float wsum[4][3];
    if ((t & 31) == 0) {
        wsum[t >> 5][0] = ss; wsum[t >> 5][1] = pp; wsum[t >> 5][2] = ab;
    }
    __syncthreads();
    float tss = wsum[0][0] + wsum[1][0] + wsum[2][0] + wsum[3][0];
    float tpp = wsum[0][1] + wsum[1][1] + wsum[2][1] + wsum[3][1];
    float tab = wsum[0][2] + wsum[1][2] + wsum[2][2] + wsum[3][2];

    float sv = SCALE_FP8 / fmaxf(sqrtf(tss), 1e-12f);
    float sw = SCALE_FP8 / fmaxf(sqrtf(tpp), 1e-12f);

    // Common swizzled-destination math for byte offset b = 4t within a row.
    int b = t * 4;
    int chunk = b >> 7;
    int off = b & 127;
    int cu = off >> 4, rem = off & 15;

    // Row `row`
    {
        uint16_t p0 = pack_e4m3x2(v.x * sv, v.y * sv);
        uint16_t p1 = pack_e4m3x2(v.z * sv, v.w * sv);
        int tileIdx = row >> 7, r = row & 127;
        size_t base = ((size_t)(tileIdx * NCHUNK + chunk) * 128 + r) * 128;
        *reinterpret_cast<uint32_t*>(z8 + base + (((cu ^ (r & 7)) << 4) + rem)) =
            (uint32_t)p0 | ((uint32_t)p1 << 16);
    }
    // Row `prow`
    {
        uint16_t p0 = pack_e4m3x2(w.x * sw, w.y * sw);
        uint16_t p1 = pack_e4m3x2(w.z * sw, w.w * sw);
        int tileIdx = prow >> 7, r = prow & 127;
        size_t base = ((size_t)(tileIdx * NCHUNK + chunk) * 128 + r) * 128;
        *reinterpret_cast<uint32_t*>(z8 + base + (((cu ^ (r & 7)) << 4) + rem)) =
            (uint32_t)p0 | ((uint32_t)p1 << 16);
    }

    if (t == 0) {
        float p = tab * rsqrtf(tss * tpp) * INV_T;
        pos[row] = p;
        pos[prow] = p;
        sumexp[row] = 0.0f;
        sumexp[prow] = 0.0f;
    }
}

// ---------------------------------------------------------------------------
// Kernel 2: fp8 MMA (f16 accum) tile kernel. Barrier-free mainloop (single
// stage reuse guarded by empty mbarrier). R14-verified addressing.
// ---------------------------------------------------------------------------
__global__ void __launch_bounds__(256, 2)
tile_kernel(const uint8_t* __restrict__ z8, float* __restrict__ sumexp,
            const float* __restrict__ pos, float* __restrict__ out) {
    extern __shared__ char smem[];
    const uint32_t sbase = smem_u32(smem);
    const int tid = threadIdx.x;
    const int lane = tid & 31;
    const int wid = tid >> 5;
    const int warpRow = wid >> 2;          // 0..1
    const int warpCol = wid & 3;           // 0..3

    // Map blockIdx.x -> upper-triangular tile (i, j), j >= i
    int t = blockIdx.x, i = 0;
    while (t >= NT - i) { t -= NT - i; ++i; }
    const int j = i + t;
    const bool diag = (i == j);
    const uint8_t* aTiles = z8 + (size_t)i * NCHUNK * CHUNK_BYTES;
    const uint8_t* bTiles = z8 + (size_t)j * NCHUNK * CHUNK_BYTES;

    // Init barriers + issue chunks 0..2 into stages 0..2.
    if (tid == 0) {
        #pragma unroll
        for (int s = 0; s < NSTAGE; ++s) mbar_init(sbase + SM_MBAR + 8 * s, 1);
        mbar_init(sbase + SM_EMPTY, 256);
        asm volatile("fence.proxy.async.shared::cta;" ::: "memory");
        #pragma unroll
        for (int s = 0; s < NSTAGE; ++s) {
            uint32_t mb = sbase + SM_MBAR + 8 * s;
            uint32_t dst = sbase + SM_TILES + s * STAGE_BYTES;
            mbar_expect_tx(mb, CHUNK_TX);
            BULK_G2S(dst,               aTiles + s * CHUNK_BYTES, CHUNK_BYTES, mb);
            BULK_G2S(dst + CHUNK_BYTES, bTiles + s * CHUNK_BYTES, CHUNK_BYTES, mb);
        }
    }
    __syncthreads();   // barrier inits visible before any wait

    // f16x2 accumulators: acc[mi][ni][h] packs cols (e=0,e=1) for row-half h.
    uint32_t acc[4][4][2];
    #pragma unroll
    for (int mi = 0; mi < 4; ++mi)
        #pragma unroll
        for (int ni = 0; ni < 4; ++ni) { acc[mi][ni][0] = 0u; acc[mi][ni][1] = 0u; }

    // Fragment addressing: row r, 16B-unit col cu -> r*128 + ((cu ^ (r&7))<<4)
    const int lane15 = lane & 15;
    const int hi = lane >> 4;
    uint32_t aRow[4], aSw[4], bRow[2], bSw[2];
    #pragma unroll
    for (int mi = 0; mi < 4; ++mi) {
        int r = warpRow * 64 + mi * 16 + lane15;
        aRow[mi] = r << 7; aSw[mi] = r & 7;
    }
    #pragma unroll
    for (int nh = 0; nh < 2; ++nh) {
        int r = warpCol * 32 + nh * 16 + lane15;
        bRow[nh] = r << 7; bSw[nh] = r & 7;
    }

    #pragma unroll
    for (int c = 0; c < NCHUNK; ++c) {
        const int s = c % NSTAGE;
        const uint32_t mb = sbase + SM_MBAR + 8 * s;
        mbar_wait(mb, (c < NSTAGE) ? 0 : 1);

        const uint32_t abase = sbase + SM_TILES + s * STAGE_BYTES;
        const uint32_t bbase = abase + CHUNK_BYTES;

        #pragma unroll
        for (int ks = 0; ks < 4; ++ks) {
            const uint32_t cu = 2 * ks + hi;
            uint32_t ra[4][4], rb[2][4];
            #pragma unroll
            for (int mi = 0; mi < 4; ++mi)
                LDMATRIX_X4(ra[mi], abase + aRow[mi] + (((cu ^ aSw[mi])) << 4));
            #pragma unroll
            for (int nh = 0; nh < 2; ++nh)
                LDMATRIX_X4(rb[nh], bbase + bRow[nh] + (((cu ^ bSw[nh])) << 4));
            #pragma unroll
            for (int mi = 0; mi < 4; ++mi)
                #pragma unroll
                for (int ni = 0; ni < 4; ++ni) {
                    const int nh = ni >> 1, sel = ni & 1;
                    MMA_FP8_F16(acc[mi][ni], ra[mi], rb[nh][sel], rb[nh][2 + sel]);
                }
        }

        // Only chunk 0's stage gets reused (chunk 3 -> stage 0): signal
        // consumption (non-blocking), and tid0 refills once all have read.
        if (c == 0) {
            mbar_arrive(sbase + SM_EMPTY);
            if (tid == 0) {
                mbar_wait(sbase + SM_EMPTY, 0);
                mbar_expect_tx(mb, CHUNK_TX);
                BULK_G2S(abase, aTiles + 3 * CHUNK_BYTES, CHUNK_BYTES, mb);
                BULK_G2S(bbase, bTiles + 3 * CHUNK_BYTES, CHUNK_BYTES, mb);
            }
        }
    }

    // Epilogue: exp2(acc) = exp(2*sim); row partials (mi,h), col partials (ni,e).
    const int m0 = warpRow * 64, n0 = warpCol * 32;
    const int rowBase = i * TM, colBase = j * TM;
    float rowp[4][2], colp[4][2];

    if (!diag) {
        __half2 rowh[4][2], colh[4];
        #pragma unroll
        for (int mi = 0; mi < 4; ++mi) { rowh[mi][0] = __half2(); rowh[mi][1] = __half2(); }
        #pragma unroll
        for (int ni = 0; ni < 4; ++ni) colh[ni] = __half2();

        #pragma unroll
        for (int mi = 0; mi < 4; ++mi)
            #pragma unroll
            for (int ni = 0; ni < 4; ++ni)
                #pragma unroll
                for (int h = 0; h < 2; ++h) {
                    __half2 ex = h2exp2(*reinterpret_cast<const __half2*>(&acc[mi][ni][h]));
                    rowh[mi][h] = __hadd2(rowh[mi][h], ex);
                    colh[ni] = __hadd2(colh[ni], ex);
                }
        #pragma unroll
        for (int mi = 0; mi < 4; ++mi)
            #pragma unroll
            for (int h = 0; h < 2; ++h) {
                float2 f = __half22float2(rowh[mi][h]);
                rowp[mi][h] = f.x + f.y;
            }
        #pragma unroll
        for (int ni = 0; ni < 4; ++ni) {
            float2 f = __half22float2(colh[ni]);
            colp[ni][0] = f.x; colp[ni][1] = f.y;
        }
    } else {
        #pragma unroll
        for (int a = 0; a < 4; ++a) { rowp[a][0] = rowp[a][1] = 0.f; colp[a][0] = colp[a][1] = 0.f; }
        #pragma unroll
        for (int mi = 0; mi < 4; ++mi)
            #pragma unroll
            for (int ni = 0; ni < 4; ++ni)
                #pragma unroll
                for (int h = 0; h < 2; ++h) {
                    float2 f = __half22float2(*reinterpret_cast<const __half2*>(&acc[mi][ni][h]));
                    #pragma unroll
                    for (int e = 0; e < 2; ++e) {
                        float ex = exp2f(e ? f.y : f.x);
                        int lr = m0 + mi * 16 + (lane >> 2) + 8 * h;
                        int lc = n0 + ni * 8 + (lane & 3) * 2 + e;
                        if (lr == lc) ex = 0.f;
                        rowp[mi][h] += ex;
                        colp[ni][e] += ex;
                    }
                }
    }

    #pragma unroll
    for (int mi = 0; mi < 4; ++mi)
        #pragma unroll
        for (int h = 0; h < 2; ++h) {
            float v = rowp[mi][h];
            v += __shfl_xor_sync(0xffffffffu, v, 1);
            v += __shfl_xor_sync(0xffffffffu, v, 2);
            rowp[mi][h] = v;
        }
    if ((lane & 3) == 0) {
        #pragma unroll
        for (int mi = 0; mi < 4; ++mi)
            #pragma unroll
            for (int h = 0; h < 2; ++h)
                atomicAdd(&sumexp[rowBase + m0 + mi * 16 + (lane >> 2) + 8 * h], rowp[mi][h]);
    }

    if (!diag) {
        #pragma unroll
        for (int ni = 0; ni < 4; ++ni)
            #pragma unroll
            for (int e = 0; e < 2; ++e) {
                float v = colp[ni][e];
                v += __shfl_xor_sync(0xffffffffu, v, 4);
                v += __shfl_xor_sync(0xffffffffu, v, 8);
                v += __shfl_xor_sync(0xffffffffu, v, 16);
                colp[ni][e] = v;
            }
        if (lane < 4) {
            #pragma unroll
            for (int ni = 0; ni < 4; ++ni)
                #pragma unroll
                for (int e = 0; e < 2; ++e)
                    atomicAdd(&sumexp[colBase + n0 + ni * 8 + lane * 2 + e], colp[ni][e]);
        }
    }

    // Last-CTA loss reduction: loss = mean( log(sumexp) - pos ).
    __threadfence();
    __shared__ int isLast;
    if (tid == 0) isLast = (atomicAdd(&g_count, 1) == NTILES - 1);
    __syncthreads();
    if (isLast) {
        float s = 0.f;
        #pragma unroll
        for (int q = 0; q < TWO_N / 256; ++q)
            s += __logf(sumexp[q * 256 + tid]) - pos[q * 256 + tid];
        #pragma unroll
        for (int off = 16; off > 0; off >>= 1)
            s += __shfl_xor_sync(0xffffffffu, s, off);
        __shared__ float wred[8];
        if (lane == 0) wred[wid] = s;
        __syncthreads();
        if (tid == 0) {
            float tot = 0.f;
            #pragma unroll
            for (int k = 0; k < 8; ++k) tot += wred[k];
            out[0] = tot * (1.0f / (float)TWO_N);
            g_count = 0;                 // reset for next graph replay
        }
    }
}

// ---------------------------------------------------------------------------
extern "C" void kernel_launch(void* const* d_in, const int* in_sizes, int n_in,
                              void* d_out, int out_size) {
    const float* z = (const float*)d_in[0];
    float* out = (float*)d_out;

    uint8_t* z8;   cudaGetSymbolAddress((void**)&z8, g_z8);
    float* sumexp; cudaGetSymbolAddress((void**)&sumexp, g_sumexp);
    float* pos;    cudaGetSymbolAddress((void**)&pos, g_pos);

    cudaFuncSetAttribute(tile_kernel, cudaFuncAttributeMaxDynamicSharedMemorySize, SMEM_BYTES);

    normpos_kernel<<<NHALF, 128>>>(z, z8, pos, sumexp);
    tile_kernel<<<NTILES, 256, SMEM_BYTES>>>(z8, sumexp, pos, out);
}